// round 1
// baseline (speedup 1.0000x reference)
#include <cuda_runtime.h>
#include <math.h>
#include <stdint.h>

// ---------------------------------------------------------------------------
// TransformerSelfAttention: B=2, S=2048, D=1024, H=16, HD=64
// out = h + mlp,  h = xn + (attn(xn) @ Wp + bp),  xn = LN1(x)
// mlp = gelu(LN2(h) @ W1 + bm1) @ W2 + bm2
// ---------------------------------------------------------------------------

#define D_MODEL 1024
#define SEQ     2048
#define BATCH   2
#define NHEAD   16
#define HDIM    64
#define MROWS   (BATCH * SEQ)        // 4096
#define DFF     (4 * D_MODEL)        // 4096

// scratch: xn, q, k, v, y, h, hn (4M floats each) + m1 (16M floats) = 44M floats
#define CH      (4u * 1024u * 1024u) // 4M floats chunk
__device__ float g_scratch[44u * 1024u * 1024u];

// ---------------------------------------------------------------------------
// LayerNorm: one block per row of 1024
// ---------------------------------------------------------------------------
__global__ void ln_kernel(const float* __restrict__ x,
                          const float* __restrict__ g,
                          const float* __restrict__ b,
                          float* __restrict__ out) {
    __shared__ float red[256], red2[256];
    __shared__ float s_mu, s_rstd;
    const int row = blockIdx.x;
    const int tid = threadIdx.x;
    const float* xr = x + (size_t)row * D_MODEL;

    float vals[4];
    float s = 0.f, s2 = 0.f;
#pragma unroll
    for (int i = 0; i < 4; i++) {
        float v = xr[tid + i * 256];
        vals[i] = v;
        s += v; s2 += v * v;
    }
    red[tid] = s; red2[tid] = s2;
    __syncthreads();
    for (int off = 128; off > 0; off >>= 1) {
        if (tid < off) { red[tid] += red[tid + off]; red2[tid] += red2[tid + off]; }
        __syncthreads();
    }
    if (tid == 0) {
        float mu = red[0] * (1.0f / D_MODEL);
        float var = red2[0] * (1.0f / D_MODEL) - mu * mu;
        s_mu = mu;
        s_rstd = rsqrtf(var + 1e-5f);
    }
    __syncthreads();
    const float mu = s_mu, rstd = s_rstd;
    float* orow = out + (size_t)row * D_MODEL;
#pragma unroll
    for (int i = 0; i < 4; i++) {
        int c = tid + i * 256;
        orow[c] = (vals[i] - mu) * rstd * g[c] + b[c];
    }
}

// ---------------------------------------------------------------------------
// SGEMM: C[M,N] = A[M,K] @ B[K,N]  (+bias over N) (gelu) (+residual[M,N])
// 128x128 tile, BK=8, 256 threads, 8x8 per thread.
// ---------------------------------------------------------------------------
template <bool GELU>
__global__ __launch_bounds__(256)
void gemm_kernel(const float* __restrict__ A, const float* __restrict__ B,
                 float* __restrict__ C, int M, int N, int K,
                 const float* __restrict__ bias,
                 const float* __restrict__ residual) {
    __shared__ float As[8][128];
    __shared__ float Bs[8][128];

    const int tid = threadIdx.x;
    const int tx = tid & 15;   // col group
    const int ty = tid >> 4;   // row group
    const int bx = blockIdx.x; // N tile
    const int by = blockIdx.y; // M tile

    const float* Ag = A + (size_t)(by * 128) * K;
    const float* Bg = B + bx * 128;

    const int arow = tid >> 1;
    const int acol = (tid & 1) * 4;
    const int brow = tid >> 5;
    const int bcol = (tid & 31) * 4;

    float acc[8][8];
#pragma unroll
    for (int i = 0; i < 8; i++)
#pragma unroll
        for (int j = 0; j < 8; j++) acc[i][j] = 0.f;

    for (int k0 = 0; k0 < K; k0 += 8) {
        float4 av = *(const float4*)(Ag + (size_t)arow * K + k0 + acol);
        As[acol + 0][arow] = av.x;
        As[acol + 1][arow] = av.y;
        As[acol + 2][arow] = av.z;
        As[acol + 3][arow] = av.w;
        *(float4*)&Bs[brow][bcol] =
            *(const float4*)(Bg + (size_t)(k0 + brow) * N + bcol);
        __syncthreads();
#pragma unroll
        for (int kk = 0; kk < 8; kk++) {
            float a[8], bb[8];
            *(float4*)&a[0]  = *(const float4*)&As[kk][ty * 8];
            *(float4*)&a[4]  = *(const float4*)&As[kk][ty * 8 + 4];
            *(float4*)&bb[0] = *(const float4*)&Bs[kk][tx * 8];
            *(float4*)&bb[4] = *(const float4*)&Bs[kk][tx * 8 + 4];
#pragma unroll
            for (int i = 0; i < 8; i++)
#pragma unroll
                for (int j = 0; j < 8; j++) acc[i][j] += a[i] * bb[j];
        }
        __syncthreads();
    }

    const int crow0 = by * 128 + ty * 8;
    const int ccol0 = bx * 128 + tx * 8;
#pragma unroll
    for (int i = 0; i < 8; i++) {
        const int row = crow0 + i;
        float* crow = C + (size_t)row * N;
        const float* rrow = residual ? residual + (size_t)row * N : nullptr;
#pragma unroll
        for (int j0 = 0; j0 < 8; j0 += 4) {
            const int col = ccol0 + j0;
            float v[4];
#pragma unroll
            for (int j = 0; j < 4; j++) v[j] = acc[i][j0 + j];
            if (bias) {
#pragma unroll
                for (int j = 0; j < 4; j++) v[j] += bias[col + j];
            }
            if (GELU) {
#pragma unroll
                for (int j = 0; j < 4; j++)
                    v[j] = 0.5f * v[j] * (1.0f + erff(v[j] * 0.70710678118654752f));
            }
            if (rrow) {
#pragma unroll
                for (int j = 0; j < 4; j++) v[j] += rrow[col + j];
            }
            float4 o; o.x = v[0]; o.y = v[1]; o.z = v[2]; o.w = v[3];
            *(float4*)(crow + col) = o;
        }
    }
}

// ---------------------------------------------------------------------------
// Flash attention: per (b,h), 64 query rows per block, online softmax,
// diagonal masked to -inf. q/k/v/y laid out [B*S, D] with head h at cols h*64.
// ---------------------------------------------------------------------------
#define QT 64
#define SPITCH 65

__global__ __launch_bounds__(256)
void attn_kernel(const float* __restrict__ q, const float* __restrict__ k,
                 const float* __restrict__ v, float* __restrict__ y) {
    extern __shared__ float sm[];
    float* sQ = sm;                       // 64 x 65
    float* sK = sQ + QT * SPITCH;
    float* sV = sK + QT * SPITCH;
    float* sS = sV + QT * SPITCH;
    float* sM = sS + QT * SPITCH;         // 64
    float* sL = sM + QT;                  // 64
    float* sA = sL + QT;                  // 64

    const int tid = threadIdx.x;
    const int tx = tid & 15;
    const int ty = tid >> 4;
    const int bh = blockIdx.x;            // 0..31
    const int b  = bh >> 4;
    const int h  = bh & 15;
    const int q0 = blockIdx.y * QT;

    const size_t base = (size_t)b * SEQ * D_MODEL + (size_t)h * HDIM;
    const float* qg = q + base;
    const float* kg = k + base;
    const float* vg = v + base;

    // load Q tile
    for (int i = tid; i < QT * 16; i += 256) {
        int r = i >> 4, c4 = (i & 15) << 2;
        float4 t = *(const float4*)(qg + (size_t)(q0 + r) * D_MODEL + c4);
        float* d = &sQ[r * SPITCH + c4];
        d[0] = t.x; d[1] = t.y; d[2] = t.z; d[3] = t.w;
    }
    if (tid < QT) { sM[tid] = -INFINITY; sL[tid] = 0.f; }

    float o[4][4];
#pragma unroll
    for (int i = 0; i < 4; i++)
#pragma unroll
        for (int j = 0; j < 4; j++) o[i][j] = 0.f;

    __syncthreads();

    for (int kt = 0; kt < SEQ / QT; kt++) {
        const int k0 = kt * QT;
        // load K, V tiles
        for (int i = tid; i < QT * 16; i += 256) {
            int r = i >> 4, c4 = (i & 15) << 2;
            float4 tk = *(const float4*)(kg + (size_t)(k0 + r) * D_MODEL + c4);
            float* dk = &sK[r * SPITCH + c4];
            dk[0] = tk.x; dk[1] = tk.y; dk[2] = tk.z; dk[3] = tk.w;
            float4 tv = *(const float4*)(vg + (size_t)(k0 + r) * D_MODEL + c4);
            float* dv = &sV[r * SPITCH + c4];
            dv[0] = tv.x; dv[1] = tv.y; dv[2] = tv.z; dv[3] = tv.w;
        }
        __syncthreads();

        // scores 64x64: thread owns rows ty*4..+3, cols tx*4..+3
        float acc[4][4];
#pragma unroll
        for (int i = 0; i < 4; i++)
#pragma unroll
            for (int j = 0; j < 4; j++) acc[i][j] = 0.f;
#pragma unroll 16
        for (int d = 0; d < HDIM; d++) {
            float aq[4], ak[4];
#pragma unroll
            for (int i = 0; i < 4; i++) aq[i] = sQ[(ty * 4 + i) * SPITCH + d];
#pragma unroll
            for (int j = 0; j < 4; j++) ak[j] = sK[(tx * 4 + j) * SPITCH + d];
#pragma unroll
            for (int i = 0; i < 4; i++)
#pragma unroll
                for (int j = 0; j < 4; j++) acc[i][j] += aq[i] * ak[j];
        }
        const float scale = 0.125f; // 1/sqrt(64)
#pragma unroll
        for (int i = 0; i < 4; i++) {
            const int gs = q0 + ty * 4 + i;
#pragma unroll
            for (int j = 0; j < 4; j++) {
                const int gt = k0 + tx * 4 + j;
                float s = acc[i][j] * scale;
                if (gs == gt) s = -INFINITY;
                sS[(ty * 4 + i) * SPITCH + tx * 4 + j] = s;
            }
        }
        __syncthreads();

        // online softmax, one thread per row
        if (tid < QT) {
            float mold = sM[tid];
            float mt = -INFINITY;
            const int rb = tid * SPITCH;
#pragma unroll 8
            for (int c = 0; c < QT; c++) mt = fmaxf(mt, sS[rb + c]);
            float mnew = fmaxf(mold, mt);
            float a = __expf(mold - mnew); // mold=-inf -> 0
            float ps = 0.f;
#pragma unroll 8
            for (int c = 0; c < QT; c++) {
                float p = __expf(sS[rb + c] - mnew);
                sS[rb + c] = p;
                ps += p;
            }
            sL[tid] = sL[tid] * a + ps;
            sM[tid] = mnew;
            sA[tid] = a;
        }
        __syncthreads();

        // O = O*alpha + P @ V
#pragma unroll
        for (int i = 0; i < 4; i++) {
            float al = sA[ty * 4 + i];
#pragma unroll
            for (int j = 0; j < 4; j++) o[i][j] *= al;
        }
#pragma unroll 16
        for (int t = 0; t < QT; t++) {
            float p[4], vv[4];
#pragma unroll
            for (int i = 0; i < 4; i++) p[i] = sS[(ty * 4 + i) * SPITCH + t];
#pragma unroll
            for (int j = 0; j < 4; j++) vv[j] = sV[t * SPITCH + tx * 4 + j];
#pragma unroll
            for (int i = 0; i < 4; i++)
#pragma unroll
                for (int j = 0; j < 4; j++) o[i][j] += p[i] * vv[j];
        }
        __syncthreads();
    }

    // normalize + store
    float* yg = y + base;
#pragma unroll
    for (int i = 0; i < 4; i++) {
        const int r = ty * 4 + i;
        const float inv = 1.0f / sL[r];
        float4 ov;
        ov.x = o[i][0] * inv; ov.y = o[i][1] * inv;
        ov.z = o[i][2] * inv; ov.w = o[i][3] * inv;
        *(float4*)(yg + (size_t)(q0 + r) * D_MODEL + tx * 4) = ov;
    }
}

// ---------------------------------------------------------------------------
// launch
// ---------------------------------------------------------------------------
extern "C" void kernel_launch(void* const* d_in, const int* in_sizes, int n_in,
                              void* d_out, int out_size) {
    const float* x   = (const float*)d_in[0];
    const float* Wk  = (const float*)d_in[1];
    const float* Wq  = (const float*)d_in[2];
    const float* Wv  = (const float*)d_in[3];
    const float* Wp  = (const float*)d_in[4];
    const float* bp  = (const float*)d_in[5];
    const float* g1  = (const float*)d_in[6];
    const float* b1  = (const float*)d_in[7];
    const float* g2  = (const float*)d_in[8];
    const float* b2  = (const float*)d_in[9];
    const float* W1  = (const float*)d_in[10];
    const float* bm1 = (const float*)d_in[11];
    const float* W2  = (const float*)d_in[12];
    const float* bm2 = (const float*)d_in[13];
    float* out = (float*)d_out;

    float* S = nullptr;
    cudaGetSymbolAddress((void**)&S, g_scratch);
    float* xn = S + 0 * CH;
    float* qb = S + 1 * CH;
    float* kb = S + 2 * CH;
    float* vb = S + 3 * CH;
    float* yb = S + 4 * CH;
    float* hb = S + 5 * CH;
    float* hn = S + 6 * CH;
    float* m1 = S + 7 * CH; // 16M floats

    const int attn_smem = (4 * QT * SPITCH + 3 * QT) * (int)sizeof(float);
    cudaFuncSetAttribute(attn_kernel, cudaFuncAttributeMaxDynamicSharedMemorySize,
                         attn_smem);

    // 1) xn = LN1(x)
    ln_kernel<<<MROWS, 256>>>(x, g1, b1, xn);

    // 2) q,k,v = xn @ Wq/Wk/Wv
    dim3 g1024(D_MODEL / 128, MROWS / 128);
    gemm_kernel<false><<<g1024, 256>>>(xn, Wq, qb, MROWS, D_MODEL, D_MODEL, nullptr, nullptr);
    gemm_kernel<false><<<g1024, 256>>>(xn, Wk, kb, MROWS, D_MODEL, D_MODEL, nullptr, nullptr);
    gemm_kernel<false><<<g1024, 256>>>(xn, Wv, vb, MROWS, D_MODEL, D_MODEL, nullptr, nullptr);

    // 3) flash attention -> yb
    dim3 ag(BATCH * NHEAD, SEQ / QT);
    attn_kernel<<<ag, 256, attn_smem>>>(qb, kb, vb, yb);

    // 4) h = xn + yb @ Wp + bp
    gemm_kernel<false><<<g1024, 256>>>(yb, Wp, hb, MROWS, D_MODEL, D_MODEL, bp, xn);

    // 5) hn = LN2(h)
    ln_kernel<<<MROWS, 256>>>(hb, g2, b2, hn);

    // 6) m1 = gelu(hn @ W1 + bm1)
    dim3 g4096(DFF / 128, MROWS / 128);
    gemm_kernel<true><<<g4096, 256>>>(hn, W1, m1, MROWS, DFF, D_MODEL, bm1, nullptr);

    // 7) out = h + m1 @ W2 + bm2
    gemm_kernel<false><<<g1024, 256>>>(m1, W2, out, MROWS, D_MODEL, DFF, bm2, hb);

    (void)in_sizes; (void)n_in; (void)out_size;
}

// round 3
// speedup vs baseline: 2.0512x; 2.0512x over previous
#include <cuda_runtime.h>
#include <math.h>
#include <stdint.h>

// ---------------------------------------------------------------------------
// TransformerSelfAttention: B=2, S=2048, D=1024, H=16, HD=64
// GEMMs via mma.sync TF32 (m16n8k8) + cp.async double buffering.
// (tcgen05 unavailable: harness lowers PTX at .target sm_103, not sm_103a)
// ---------------------------------------------------------------------------

#define D_MODEL 1024
#define SEQ     2048
#define BATCH   2
#define NHEAD   16
#define HDIM    64
#define MROWS   (BATCH * SEQ)        // 4096
#define DFF     (4 * D_MODEL)        // 4096

#define CH      (4u * 1024u * 1024u) // 4M floats chunk
// 0:xn 1:xnr 2:q 3:k 4:v 5:y 6:h 7:hn 8-11:m1 12:WqT 13:WkT 14:WvT 15:WpT
// 16-19:W1T 20-23:W2T   -> 96M floats
__device__ float g_scratch[96u * 1024u * 1024u];

// ===========================================================================
// helpers
// ===========================================================================
__device__ __forceinline__ uint32_t smem_u32(const void* p) {
    uint32_t a;
    asm("{ .reg .u64 t; cvta.to.shared.u64 t, %1; cvt.u32.u64 %0, t; }"
        : "=r"(a) : "l"(p));
    return a;
}
// unbiased fp32 -> tf32 rounding (round-to-nearest-even on 10-bit mantissa)
__device__ __forceinline__ float tf32r(float x) {
    uint32_t o;
    asm("cvt.rna.tf32.f32 %0, %1;" : "=r"(o) : "f"(x));
    return __uint_as_float(o);
}

#define CP_ASYNC16(dst, src) \
    asm volatile("cp.async.cg.shared.global [%0], [%1], 16;" \
                 :: "r"(dst), "l"(src))
#define CP_COMMIT()  asm volatile("cp.async.commit_group;")
#define CP_WAIT0()   asm volatile("cp.async.wait_group 0;")

__device__ __forceinline__ void mma_tf32(float* c, const uint32_t* a,
                                         const uint32_t* b) {
    asm volatile(
        "mma.sync.aligned.m16n8k8.row.col.f32.tf32.tf32.f32 "
        "{%0,%1,%2,%3}, {%4,%5,%6,%7}, {%8,%9}, {%0,%1,%2,%3};"
        : "+f"(c[0]), "+f"(c[1]), "+f"(c[2]), "+f"(c[3])
        : "r"(a[0]), "r"(a[1]), "r"(a[2]), "r"(a[3]), "r"(b[0]), "r"(b[1]));
}

// ===========================================================================
// LayerNorm: one block per row of 1024. Optional exact + tf32-rounded outputs.
// ===========================================================================
__global__ void ln_kernel(const float* __restrict__ x,
                          const float* __restrict__ g,
                          const float* __restrict__ b,
                          float* __restrict__ out,
                          float* __restrict__ outr) {
    __shared__ float red[256], red2[256];
    __shared__ float s_mu, s_rstd;
    const int row = blockIdx.x;
    const int tid = threadIdx.x;
    const float* xr = x + (size_t)row * D_MODEL;

    float vals[4];
    float s = 0.f, s2 = 0.f;
#pragma unroll
    for (int i = 0; i < 4; i++) {
        float v = xr[tid + i * 256];
        vals[i] = v;
        s += v; s2 += v * v;
    }
    red[tid] = s; red2[tid] = s2;
    __syncthreads();
    for (int off = 128; off > 0; off >>= 1) {
        if (tid < off) { red[tid] += red[tid + off]; red2[tid] += red2[tid + off]; }
        __syncthreads();
    }
    if (tid == 0) {
        float mu = red[0] * (1.0f / D_MODEL);
        float var = red2[0] * (1.0f / D_MODEL) - mu * mu;
        s_mu = mu;
        s_rstd = rsqrtf(var + 1e-5f);
    }
    __syncthreads();
    const float mu = s_mu, rstd = s_rstd;
#pragma unroll
    for (int i = 0; i < 4; i++) {
        int c = tid + i * 256;
        float v = (vals[i] - mu) * rstd * g[c] + b[c];
        if (out)  out[(size_t)row * D_MODEL + c] = v;
        if (outr) outr[(size_t)row * D_MODEL + c] = tf32r(v);
    }
}

// ===========================================================================
// Transpose + tf32 round: out[C,R] = tf32(in[R,C]^T)
// ===========================================================================
__global__ void transpose_kernel(const float* __restrict__ in,
                                 float* __restrict__ out, int R, int C) {
    __shared__ float t[32][33];
    const int bx = blockIdx.x * 32, by = blockIdx.y * 32;
    const int tx = threadIdx.x, ty = threadIdx.y;
#pragma unroll
    for (int j = 0; j < 32; j += 8)
        t[ty + j][tx] = in[(size_t)(by + ty + j) * C + bx + tx];
    __syncthreads();
#pragma unroll
    for (int j = 0; j < 32; j += 8)
        out[(size_t)(bx + ty + j) * R + by + tx] = tf32r(t[tx][ty + j]);
}

// ===========================================================================
// TF32 mma.sync GEMM: C[M,N] = A[M,K] @ Bt[N,K]^T  (+bias)(gelu)(+residual)
// 128x128 CTA tile, BK=32, 256 thr (8 warps, 2Mx4N, warp tile 64x32),
// cp.async double buffer, padded SMEM (stride 36 floats).
// ===========================================================================
#define LDSA 36                        // floats per SMEM row
#define TILE_F (128 * LDSA)            // 4608 floats / tile
#define STAGE_F (2 * TILE_F)           // A + B
#define GEMM_SMEM (2 * STAGE_F * 4)    // 73728 bytes

__device__ __forceinline__ void tile_load(const float* __restrict__ Ag,
                                          const float* __restrict__ Bg,
                                          int K, int it, uint32_t sbu, int tid) {
    const uint32_t dst = sbu + (uint32_t)(it & 1) * (STAGE_F * 4);
#pragma unroll
    for (int j = 0; j < 4; j++) {
        const int idx = tid + j * 256;        // 0..1023
        const int row = idx >> 3;
        const int c8 = idx & 7;
        const uint32_t so = (uint32_t)(row * LDSA + c8 * 4) * 4u;
        const float* ga = Ag + (size_t)row * K + it * 32 + c8 * 4;
        const float* gb = Bg + (size_t)row * K + it * 32 + c8 * 4;
        CP_ASYNC16(dst + so, ga);
        CP_ASYNC16(dst + TILE_F * 4 + so, gb);
    }
    CP_COMMIT();
}

template <bool GELU>
__global__ __launch_bounds__(256)
void tgemm(const float* __restrict__ A, const float* __restrict__ Bt,
           float* __restrict__ C, int M, int N, int K,
           const float* __restrict__ bias, const float* __restrict__ residual) {
    extern __shared__ float sm[];
    const uint32_t sbu = smem_u32(sm);

    const int tid = threadIdx.x;
    const int w = tid >> 5, lane = tid & 31;
    const int g = lane >> 2, t = lane & 3;
    const int wm = w & 1, wn = w >> 1;        // 2 x 4 warps
    const int m0 = blockIdx.y * 128, n0 = blockIdx.x * 128;
    const float* Ag = A + (size_t)m0 * K;
    const float* Bg = Bt + (size_t)n0 * K;
    const int nk = K >> 5;

    float c[4][4][4];
#pragma unroll
    for (int i = 0; i < 4; i++)
#pragma unroll
        for (int j = 0; j < 4; j++)
#pragma unroll
            for (int q = 0; q < 4; q++) c[i][j][q] = 0.f;

    tile_load(Ag, Bg, K, 0, sbu, tid);

    for (int it = 0; it < nk; it++) {
        CP_WAIT0();
        __syncthreads();
        if (it + 1 < nk) tile_load(Ag, Bg, K, it + 1, sbu, tid);

        const float* a = sm + (it & 1) * STAGE_F;
        const float* b = a + TILE_F;
#pragma unroll
        for (int ks = 0; ks < 4; ks++) {
            const int k0 = ks * 8;
            uint32_t ar[4][4];
#pragma unroll
            for (int mf = 0; mf < 4; mf++) {
                const float* ap = a + (wm * 64 + mf * 16 + g) * LDSA + k0 + t;
                ar[mf][0] = __float_as_uint(ap[0]);
                ar[mf][1] = __float_as_uint(ap[8 * LDSA]);
                ar[mf][2] = __float_as_uint(ap[4]);
                ar[mf][3] = __float_as_uint(ap[8 * LDSA + 4]);
            }
            uint32_t br[4][2];
#pragma unroll
            for (int nf = 0; nf < 4; nf++) {
                const float* bp = b + (wn * 32 + nf * 8 + g) * LDSA + k0 + t;
                br[nf][0] = __float_as_uint(bp[0]);
                br[nf][1] = __float_as_uint(bp[4]);
            }
#pragma unroll
            for (int mf = 0; mf < 4; mf++)
#pragma unroll
                for (int nf = 0; nf < 4; nf++)
                    mma_tf32(c[mf][nf], ar[mf], br[nf]);
        }
        __syncthreads();
    }

    // epilogue
#pragma unroll
    for (int mf = 0; mf < 4; mf++) {
        const int r0 = m0 + wm * 64 + mf * 16 + g;
#pragma unroll
        for (int half = 0; half < 2; half++) {
            const int row = r0 + half * 8;
            float* crow = C + (size_t)row * N;
            const float* rrow = residual ? residual + (size_t)row * N : nullptr;
#pragma unroll
            for (int nf = 0; nf < 4; nf++) {
                const int col = n0 + wn * 32 + nf * 8 + t * 2;
                float v0 = c[mf][nf][half * 2 + 0];
                float v1 = c[mf][nf][half * 2 + 1];
                if (bias) { v0 += bias[col]; v1 += bias[col + 1]; }
                if (GELU) {
                    v0 = 0.5f * v0 * (1.0f + erff(v0 * 0.70710678118654752f));
                    v1 = 0.5f * v1 * (1.0f + erff(v1 * 0.70710678118654752f));
                    v0 = tf32r(v0); v1 = tf32r(v1); // feeds next tf32 GEMM
                }
                if (rrow) { v0 += rrow[col]; v1 += rrow[col + 1]; }
                float2 o; o.x = v0; o.y = v1;
                *(float2*)(crow + col) = o;
            }
        }
    }
    (void)M;
}

// ===========================================================================
// Flash attention (fp32), 64 q-rows/block, diagonal masked; output tf32-round
// ===========================================================================
#define QT 64
#define SPITCH 65

__global__ __launch_bounds__(256)
void attn_kernel(const float* __restrict__ q, const float* __restrict__ k,
                 const float* __restrict__ v, float* __restrict__ y) {
    extern __shared__ float sm[];
    float* sQ = sm;
    float* sK = sQ + QT * SPITCH;
    float* sV = sK + QT * SPITCH;
    float* sS = sV + QT * SPITCH;
    float* sM = sS + QT * SPITCH;
    float* sL = sM + QT;
    float* sA = sL + QT;

    const int tid = threadIdx.x;
    const int tx = tid & 15;
    const int ty = tid >> 4;
    const int bh = blockIdx.x;
    const int b  = bh >> 4;
    const int h  = bh & 15;
    const int q0 = blockIdx.y * QT;

    const size_t base = (size_t)b * SEQ * D_MODEL + (size_t)h * HDIM;
    const float* qg = q + base;
    const float* kg = k + base;
    const float* vg = v + base;

    for (int i = tid; i < QT * 16; i += 256) {
        int r = i >> 4, c4 = (i & 15) << 2;
        float4 t = *(const float4*)(qg + (size_t)(q0 + r) * D_MODEL + c4);
        float* d = &sQ[r * SPITCH + c4];
        d[0] = t.x; d[1] = t.y; d[2] = t.z; d[3] = t.w;
    }
    if (tid < QT) { sM[tid] = -INFINITY; sL[tid] = 0.f; }

    float o[4][4];
#pragma unroll
    for (int i = 0; i < 4; i++)
#pragma unroll
        for (int j = 0; j < 4; j++) o[i][j] = 0.f;

    __syncthreads();

    for (int kt = 0; kt < SEQ / QT; kt++) {
        const int k0 = kt * QT;
        for (int i = tid; i < QT * 16; i += 256) {
            int r = i >> 4, c4 = (i & 15) << 2;
            float4 tk = *(const float4*)(kg + (size_t)(k0 + r) * D_MODEL + c4);
            float* dk = &sK[r * SPITCH + c4];
            dk[0] = tk.x; dk[1] = tk.y; dk[2] = tk.z; dk[3] = tk.w;
            float4 tv = *(const float4*)(vg + (size_t)(k0 + r) * D_MODEL + c4);
            float* dv = &sV[r * SPITCH + c4];
            dv[0] = tv.x; dv[1] = tv.y; dv[2] = tv.z; dv[3] = tv.w;
        }
        __syncthreads();

        float acc[4][4];
#pragma unroll
        for (int i = 0; i < 4; i++)
#pragma unroll
            for (int j = 0; j < 4; j++) acc[i][j] = 0.f;
#pragma unroll 16
        for (int d = 0; d < HDIM; d++) {
            float aq[4], ak[4];
#pragma unroll
            for (int i = 0; i < 4; i++) aq[i] = sQ[(ty * 4 + i) * SPITCH + d];
#pragma unroll
            for (int j = 0; j < 4; j++) ak[j] = sK[(tx * 4 + j) * SPITCH + d];
#pragma unroll
            for (int i = 0; i < 4; i++)
#pragma unroll
                for (int j = 0; j < 4; j++) acc[i][j] += aq[i] * ak[j];
        }
        const float scale = 0.125f;
#pragma unroll
        for (int i = 0; i < 4; i++) {
            const int gs = q0 + ty * 4 + i;
#pragma unroll
            for (int j = 0; j < 4; j++) {
                const int gt = k0 + tx * 4 + j;
                float s = acc[i][j] * scale;
                if (gs == gt) s = -INFINITY;
                sS[(ty * 4 + i) * SPITCH + tx * 4 + j] = s;
            }
        }
        __syncthreads();

        if (tid < QT) {
            float mold = sM[tid];
            float mt = -INFINITY;
            const int rb = tid * SPITCH;
#pragma unroll 8
            for (int c = 0; c < QT; c++) mt = fmaxf(mt, sS[rb + c]);
            float mnew = fmaxf(mold, mt);
            float a = __expf(mold - mnew);
            float ps = 0.f;
#pragma unroll 8
            for (int c = 0; c < QT; c++) {
                float p = __expf(sS[rb + c] - mnew);
                sS[rb + c] = p;
                ps += p;
            }
            sL[tid] = sL[tid] * a + ps;
            sM[tid] = mnew;
            sA[tid] = a;
        }
        __syncthreads();

#pragma unroll
        for (int i = 0; i < 4; i++) {
            float al = sA[ty * 4 + i];
#pragma unroll
            for (int j = 0; j < 4; j++) o[i][j] *= al;
        }
#pragma unroll 16
        for (int t = 0; t < QT; t++) {
            float p[4], vv[4];
#pragma unroll
            for (int i = 0; i < 4; i++) p[i] = sS[(ty * 4 + i) * SPITCH + t];
#pragma unroll
            for (int j = 0; j < 4; j++) vv[j] = sV[t * SPITCH + tx * 4 + j];
#pragma unroll
            for (int i = 0; i < 4; i++)
#pragma unroll
                for (int j = 0; j < 4; j++) o[i][j] += p[i] * vv[j];
        }
        __syncthreads();
    }

    float* yg = y + base;
#pragma unroll
    for (int i = 0; i < 4; i++) {
        const int r = ty * 4 + i;
        const float inv = 1.0f / sL[r];
        float4 ov;
        ov.x = tf32r(o[i][0] * inv); ov.y = tf32r(o[i][1] * inv);
        ov.z = tf32r(o[i][2] * inv); ov.w = tf32r(o[i][3] * inv);
        *(float4*)(yg + (size_t)(q0 + r) * D_MODEL + tx * 4) = ov;
    }
}

// ===========================================================================
// launch
// ===========================================================================
extern "C" void kernel_launch(void* const* d_in, const int* in_sizes, int n_in,
                              void* d_out, int out_size) {
    const float* x   = (const float*)d_in[0];
    const float* Wk  = (const float*)d_in[1];
    const float* Wq  = (const float*)d_in[2];
    const float* Wv  = (const float*)d_in[3];
    const float* Wp  = (const float*)d_in[4];
    const float* bp  = (const float*)d_in[5];
    const float* g1  = (const float*)d_in[6];
    const float* b1  = (const float*)d_in[7];
    const float* g2  = (const float*)d_in[8];
    const float* b2  = (const float*)d_in[9];
    const float* W1  = (const float*)d_in[10];
    const float* bm1 = (const float*)d_in[11];
    const float* W2  = (const float*)d_in[12];
    const float* bm2 = (const float*)d_in[13];
    float* out = (float*)d_out;

    float* S = nullptr;
    cudaGetSymbolAddress((void**)&S, g_scratch);
    float* xn  = S + 0 * CH;
    float* xnr = S + 1 * CH;
    float* qb  = S + 2 * CH;
    float* kb  = S + 3 * CH;
    float* vb  = S + 4 * CH;
    float* yb  = S + 5 * CH;
    float* hb  = S + 6 * CH;
    float* hn  = S + 7 * CH;
    float* m1  = S + 8 * CH;   // 16M floats
    float* WqT = S + 12 * CH;
    float* WkT = S + 13 * CH;
    float* WvT = S + 14 * CH;
    float* WpT = S + 15 * CH;
    float* W1T = S + 16 * CH;  // 4M
    float* W2T = S + 20 * CH;  // 4M

    const int attn_smem = (4 * QT * SPITCH + 3 * QT) * (int)sizeof(float);
    cudaFuncSetAttribute(attn_kernel, cudaFuncAttributeMaxDynamicSharedMemorySize,
                         attn_smem);
    cudaFuncSetAttribute(tgemm<false>, cudaFuncAttributeMaxDynamicSharedMemorySize,
                         GEMM_SMEM);
    cudaFuncSetAttribute(tgemm<true>, cudaFuncAttributeMaxDynamicSharedMemorySize,
                         GEMM_SMEM);

    // 0) transpose weights -> [N,K], tf32-rounded
    dim3 tb(32, 8);
    transpose_kernel<<<dim3(D_MODEL/32, D_MODEL/32), tb>>>(Wq, WqT, D_MODEL, D_MODEL);
    transpose_kernel<<<dim3(D_MODEL/32, D_MODEL/32), tb>>>(Wk, WkT, D_MODEL, D_MODEL);
    transpose_kernel<<<dim3(D_MODEL/32, D_MODEL/32), tb>>>(Wv, WvT, D_MODEL, D_MODEL);
    transpose_kernel<<<dim3(D_MODEL/32, D_MODEL/32), tb>>>(Wp, WpT, D_MODEL, D_MODEL);
    transpose_kernel<<<dim3(DFF/32, D_MODEL/32),     tb>>>(W1, W1T, D_MODEL, DFF);
    transpose_kernel<<<dim3(D_MODEL/32, DFF/32),     tb>>>(W2, W2T, DFF, D_MODEL);

    // 1) xn = LN1(x): exact (residual) + rounded (GEMM A)
    ln_kernel<<<MROWS, 256>>>(x, g1, b1, xn, xnr);

    // 2) q,k,v = xnr @ W
    dim3 g1024(D_MODEL / 128, MROWS / 128);
    tgemm<false><<<g1024, 256, GEMM_SMEM>>>(xnr, WqT, qb, MROWS, D_MODEL, D_MODEL, nullptr, nullptr);
    tgemm<false><<<g1024, 256, GEMM_SMEM>>>(xnr, WkT, kb, MROWS, D_MODEL, D_MODEL, nullptr, nullptr);
    tgemm<false><<<g1024, 256, GEMM_SMEM>>>(xnr, WvT, vb, MROWS, D_MODEL, D_MODEL, nullptr, nullptr);

    // 3) flash attention -> yb (tf32-rounded)
    dim3 ag(BATCH * NHEAD, SEQ / QT);
    attn_kernel<<<ag, 256, attn_smem>>>(qb, kb, vb, yb);

    // 4) h = xn + yb @ Wp + bp
    tgemm<false><<<g1024, 256, GEMM_SMEM>>>(yb, WpT, hb, MROWS, D_MODEL, D_MODEL, bp, xn);

    // 5) hn = LN2(h), rounded only (GEMM input)
    ln_kernel<<<MROWS, 256>>>(hb, g2, b2, nullptr, hn);

    // 6) m1 = tf32(gelu(hn @ W1 + bm1))
    dim3 g4096(DFF / 128, MROWS / 128);
    tgemm<true><<<g4096, 256, GEMM_SMEM>>>(hn, W1T, m1, MROWS, DFF, D_MODEL, bm1, nullptr);

    // 7) out = hb + m1 @ W2 + bm2
    tgemm<false><<<g1024, 256, GEMM_SMEM>>>(m1, W2T, out, MROWS, D_MODEL, DFF, bm2, hb);

    (void)in_sizes; (void)n_in; (void)out_size;
}

// round 4
// speedup vs baseline: 3.0196x; 1.4721x over previous
#include <cuda_runtime.h>
#include <math.h>
#include <stdint.h>

// ---------------------------------------------------------------------------
// TransformerSelfAttention: B=2, S=2048, D=1024, H=16, HD=64
// GEMMs + attention on mma.sync TF32 (m16n8k8), cp.async double buffering.
// ---------------------------------------------------------------------------

#define D_MODEL 1024
#define SEQ     2048
#define BATCH   2
#define NHEAD   16
#define HDIM    64
#define MROWS   (BATCH * SEQ)        // 4096
#define DFF     (4 * D_MODEL)        // 4096

#define CH      (4u * 1024u * 1024u) // 4M floats chunk
__device__ float g_scratch[96u * 1024u * 1024u];

// ===========================================================================
// helpers
// ===========================================================================
__device__ __forceinline__ uint32_t smem_u32(const void* p) {
    uint32_t a;
    asm("{ .reg .u64 t; cvta.to.shared.u64 t, %1; cvt.u32.u64 %0, t; }"
        : "=r"(a) : "l"(p));
    return a;
}
// unbiased fp32 -> tf32 rounding
__device__ __forceinline__ float tf32r(float x) {
    uint32_t o;
    asm("cvt.rna.tf32.f32 %0, %1;" : "=r"(o) : "f"(x));
    return __uint_as_float(o);
}

#define CP_ASYNC16(dst, src) \
    asm volatile("cp.async.cg.shared.global [%0], [%1], 16;" \
                 :: "r"(dst), "l"(src))
#define CP_COMMIT()  asm volatile("cp.async.commit_group;")
#define CP_WAIT0()   asm volatile("cp.async.wait_group 0;")

__device__ __forceinline__ void mma_tf32(float* c, const uint32_t* a,
                                         const uint32_t* b) {
    asm volatile(
        "mma.sync.aligned.m16n8k8.row.col.f32.tf32.tf32.f32 "
        "{%0,%1,%2,%3}, {%4,%5,%6,%7}, {%8,%9}, {%0,%1,%2,%3};"
        : "+f"(c[0]), "+f"(c[1]), "+f"(c[2]), "+f"(c[3])
        : "r"(a[0]), "r"(a[1]), "r"(a[2]), "r"(a[3]), "r"(b[0]), "r"(b[1]));
}

// ===========================================================================
// LayerNorm
// ===========================================================================
__global__ void ln_kernel(const float* __restrict__ x,
                          const float* __restrict__ g,
                          const float* __restrict__ b,
                          float* __restrict__ out,
                          float* __restrict__ outr) {
    __shared__ float red[256], red2[256];
    __shared__ float s_mu, s_rstd;
    const int row = blockIdx.x;
    const int tid = threadIdx.x;
    const float* xr = x + (size_t)row * D_MODEL;

    float vals[4];
    float s = 0.f, s2 = 0.f;
#pragma unroll
    for (int i = 0; i < 4; i++) {
        float v = xr[tid + i * 256];
        vals[i] = v;
        s += v; s2 += v * v;
    }
    red[tid] = s; red2[tid] = s2;
    __syncthreads();
    for (int off = 128; off > 0; off >>= 1) {
        if (tid < off) { red[tid] += red[tid + off]; red2[tid] += red2[tid + off]; }
        __syncthreads();
    }
    if (tid == 0) {
        float mu = red[0] * (1.0f / D_MODEL);
        float var = red2[0] * (1.0f / D_MODEL) - mu * mu;
        s_mu = mu;
        s_rstd = rsqrtf(var + 1e-5f);
    }
    __syncthreads();
    const float mu = s_mu, rstd = s_rstd;
#pragma unroll
    for (int i = 0; i < 4; i++) {
        int c = tid + i * 256;
        float v = (vals[i] - mu) * rstd * g[c] + b[c];
        if (out)  out[(size_t)row * D_MODEL + c] = v;
        if (outr) outr[(size_t)row * D_MODEL + c] = tf32r(v);
    }
}

// ===========================================================================
// Transpose + tf32 round
// ===========================================================================
__global__ void transpose_kernel(const float* __restrict__ in,
                                 float* __restrict__ out, int R, int C) {
    __shared__ float t[32][33];
    const int bx = blockIdx.x * 32, by = blockIdx.y * 32;
    const int tx = threadIdx.x, ty = threadIdx.y;
#pragma unroll
    for (int j = 0; j < 32; j += 8)
        t[ty + j][tx] = in[(size_t)(by + ty + j) * C + bx + tx];
    __syncthreads();
#pragma unroll
    for (int j = 0; j < 32; j += 8)
        out[(size_t)(bx + ty + j) * R + by + tx] = tf32r(t[tx][ty + j]);
}

// ===========================================================================
// TF32 mma.sync GEMM (unchanged from round 3)
// ===========================================================================
#define LDSA 36
#define TILE_F (128 * LDSA)
#define STAGE_F (2 * TILE_F)
#define GEMM_SMEM (2 * STAGE_F * 4)

__device__ __forceinline__ void tile_load(const float* __restrict__ Ag,
                                          const float* __restrict__ Bg,
                                          int K, int it, uint32_t sbu, int tid) {
    const uint32_t dst = sbu + (uint32_t)(it & 1) * (STAGE_F * 4);
#pragma unroll
    for (int j = 0; j < 4; j++) {
        const int idx = tid + j * 256;
        const int row = idx >> 3;
        const int c8 = idx & 7;
        const uint32_t so = (uint32_t)(row * LDSA + c8 * 4) * 4u;
        const float* ga = Ag + (size_t)row * K + it * 32 + c8 * 4;
        const float* gb = Bg + (size_t)row * K + it * 32 + c8 * 4;
        CP_ASYNC16(dst + so, ga);
        CP_ASYNC16(dst + TILE_F * 4 + so, gb);
    }
    CP_COMMIT();
}

template <bool GELU>
__global__ __launch_bounds__(256)
void tgemm(const float* __restrict__ A, const float* __restrict__ Bt,
           float* __restrict__ C, int M, int N, int K,
           const float* __restrict__ bias, const float* __restrict__ residual) {
    extern __shared__ float sm[];
    const uint32_t sbu = smem_u32(sm);

    const int tid = threadIdx.x;
    const int w = tid >> 5, lane = tid & 31;
    const int g = lane >> 2, t = lane & 3;
    const int wm = w & 1, wn = w >> 1;
    const int m0 = blockIdx.y * 128, n0 = blockIdx.x * 128;
    const float* Ag = A + (size_t)m0 * K;
    const float* Bg = Bt + (size_t)n0 * K;
    const int nk = K >> 5;

    float c[4][4][4];
#pragma unroll
    for (int i = 0; i < 4; i++)
#pragma unroll
        for (int j = 0; j < 4; j++)
#pragma unroll
            for (int q = 0; q < 4; q++) c[i][j][q] = 0.f;

    tile_load(Ag, Bg, K, 0, sbu, tid);

    for (int it = 0; it < nk; it++) {
        CP_WAIT0();
        __syncthreads();
        if (it + 1 < nk) tile_load(Ag, Bg, K, it + 1, sbu, tid);

        const float* a = sm + (it & 1) * STAGE_F;
        const float* b = a + TILE_F;
#pragma unroll
        for (int ks = 0; ks < 4; ks++) {
            const int k0 = ks * 8;
            uint32_t ar[4][4];
#pragma unroll
            for (int mf = 0; mf < 4; mf++) {
                const float* ap = a + (wm * 64 + mf * 16 + g) * LDSA + k0 + t;
                ar[mf][0] = __float_as_uint(ap[0]);
                ar[mf][1] = __float_as_uint(ap[8 * LDSA]);
                ar[mf][2] = __float_as_uint(ap[4]);
                ar[mf][3] = __float_as_uint(ap[8 * LDSA + 4]);
            }
            uint32_t br[4][2];
#pragma unroll
            for (int nf = 0; nf < 4; nf++) {
                const float* bp = b + (wn * 32 + nf * 8 + g) * LDSA + k0 + t;
                br[nf][0] = __float_as_uint(bp[0]);
                br[nf][1] = __float_as_uint(bp[4]);
            }
#pragma unroll
            for (int mf = 0; mf < 4; mf++)
#pragma unroll
                for (int nf = 0; nf < 4; nf++)
                    mma_tf32(c[mf][nf], ar[mf], br[nf]);
        }
        __syncthreads();
    }

#pragma unroll
    for (int mf = 0; mf < 4; mf++) {
        const int r0 = m0 + wm * 64 + mf * 16 + g;
#pragma unroll
        for (int half = 0; half < 2; half++) {
            const int row = r0 + half * 8;
            float* crow = C + (size_t)row * N;
            const float* rrow = residual ? residual + (size_t)row * N : nullptr;
#pragma unroll
            for (int nf = 0; nf < 4; nf++) {
                const int col = n0 + wn * 32 + nf * 8 + t * 2;
                float v0 = c[mf][nf][half * 2 + 0];
                float v1 = c[mf][nf][half * 2 + 1];
                if (bias) { v0 += bias[col]; v1 += bias[col + 1]; }
                if (GELU) {
                    v0 = 0.5f * v0 * (1.0f + erff(v0 * 0.70710678118654752f));
                    v1 = 0.5f * v1 * (1.0f + erff(v1 * 0.70710678118654752f));
                    v0 = tf32r(v0); v1 = tf32r(v1);
                }
                if (rrow) { v0 += rrow[col]; v1 += rrow[col + 1]; }
                float2 o; o.x = v0; o.y = v1;
                *(float2*)(crow + col) = o;
            }
        }
    }
    (void)M;
}

// ===========================================================================
// Flash attention on mma.sync TF32.
// Per CTA: one (b,h), 64 q-rows, 4 warps (each m16 x n64 fragments).
// sVt holds V transposed so PV maps onto row.col mma. Softmax 2 thr/row.
// ===========================================================================
#define ALD 68   // floats per SMEM row (4g+t bank-distinct for frag loads)
#define ATT_SMEM ((4 * 64 * ALD + 3 * 64) * 4)

__global__ __launch_bounds__(128)
void attn_kernel(const float* __restrict__ q, const float* __restrict__ k,
                 const float* __restrict__ v, float* __restrict__ y) {
    extern __shared__ float sm[];
    float* sQ  = sm;                  // 64 x ALD
    float* sK  = sQ  + 64 * ALD;
    float* sVt = sK  + 64 * ALD;      // transposed V: sVt[d][t]
    float* sP  = sVt + 64 * ALD;
    float* sM  = sP  + 64 * ALD;      // 64
    float* sL  = sM + 64;
    float* sA  = sL + 64;

    const int tid  = threadIdx.x;
    const int wid  = tid >> 5;
    const int lane = tid & 31;
    const int g = lane >> 2, t = lane & 3;
    const int wm0 = wid * 16;

    const int bh = blockIdx.x;
    const int b  = bh >> 4;
    const int h  = bh & 15;
    const int q0 = blockIdx.y * 64;

    const size_t base = (size_t)b * SEQ * D_MODEL + (size_t)h * HDIM;
    const float* qg = q + base;
    const float* kg = k + base;
    const float* vg = v + base;

    // load Q once (tf32-rounded)
#pragma unroll
    for (int j = 0; j < 8; j++) {
        const int idx = tid + j * 128;
        const int r = idx >> 4, c4 = (idx & 15) << 2;
        float4 tq = *(const float4*)(qg + (size_t)(q0 + r) * D_MODEL + c4);
        float* d = &sQ[r * ALD + c4];
        d[0] = tf32r(tq.x); d[1] = tf32r(tq.y);
        d[2] = tf32r(tq.z); d[3] = tf32r(tq.w);
    }
    if (tid < 64) { sM[tid] = -INFINITY; sL[tid] = 0.f; }

    float o[8][4];
#pragma unroll
    for (int i = 0; i < 8; i++)
#pragma unroll
        for (int j = 0; j < 4; j++) o[i][j] = 0.f;

    __syncthreads();

    for (int kt = 0; kt < SEQ / 64; kt++) {
        const int k0 = kt * 64;
        // load K (rounded) and V transposed (rounded)
#pragma unroll
        for (int j = 0; j < 8; j++) {
            const int idx = tid + j * 128;
            const int r = idx >> 4, c4 = (idx & 15) << 2;
            float4 tk = *(const float4*)(kg + (size_t)(k0 + r) * D_MODEL + c4);
            float* dk = &sK[r * ALD + c4];
            dk[0] = tf32r(tk.x); dk[1] = tf32r(tk.y);
            dk[2] = tf32r(tk.z); dk[3] = tf32r(tk.w);
            float4 tv = *(const float4*)(vg + (size_t)(k0 + r) * D_MODEL + c4);
            sVt[(c4 + 0) * ALD + r] = tf32r(tv.x);
            sVt[(c4 + 1) * ALD + r] = tf32r(tv.y);
            sVt[(c4 + 2) * ALD + r] = tf32r(tv.z);
            sVt[(c4 + 3) * ALD + r] = tf32r(tv.w);
        }
        __syncthreads();

        // S = Q @ K^T  (m16 x n64, K=64)
        float sacc[8][4];
#pragma unroll
        for (int i = 0; i < 8; i++)
#pragma unroll
            for (int j = 0; j < 4; j++) sacc[i][j] = 0.f;
#pragma unroll
        for (int ks = 0; ks < 8; ks++) {
            const int kk = ks * 8;
            uint32_t a[4];
            const float* ap = sQ + (wm0 + g) * ALD + kk + t;
            a[0] = __float_as_uint(ap[0]);
            a[1] = __float_as_uint(ap[8 * ALD]);
            a[2] = __float_as_uint(ap[4]);
            a[3] = __float_as_uint(ap[8 * ALD + 4]);
#pragma unroll
            for (int nf = 0; nf < 8; nf++) {
                uint32_t bb[2];
                const float* bp = sK + (nf * 8 + g) * ALD + kk + t;
                bb[0] = __float_as_uint(bp[0]);
                bb[1] = __float_as_uint(bp[4]);
                mma_tf32(sacc[nf], a, bb);
            }
        }

        // scale + diag mask -> sP
        const float scale = 0.125f;
#pragma unroll
        for (int nf = 0; nf < 8; nf++) {
            const int col = nf * 8 + t * 2;
#pragma unroll
            for (int half = 0; half < 2; half++) {
                const int r = wm0 + g + half * 8;
                float v0 = sacc[nf][half * 2 + 0] * scale;
                float v1 = sacc[nf][half * 2 + 1] * scale;
                if (q0 + r == k0 + col)     v0 = -INFINITY;
                if (q0 + r == k0 + col + 1) v1 = -INFINITY;
                float2 pv; pv.x = v0; pv.y = v1;
                *(float2*)(sP + r * ALD + col) = pv;
            }
        }
        __syncthreads();

        // online softmax: 2 threads per row (each 32 cols), shfl combine
        {
            const int r = tid >> 1, hf = tid & 1;
            float* row = sP + r * ALD + hf * 32;
            float mt = -INFINITY;
#pragma unroll 8
            for (int c = 0; c < 32; c++) mt = fmaxf(mt, row[c]);
            mt = fmaxf(mt, __shfl_xor_sync(0xffffffffu, mt, 1));
            const float mold = sM[r];
            const float mnew = fmaxf(mold, mt);
            float ps = 0.f;
#pragma unroll 8
            for (int c = 0; c < 32; c++) {
                float p = __expf(row[c] - mnew);
                row[c] = tf32r(p);
                ps += p;
            }
            ps += __shfl_xor_sync(0xffffffffu, ps, 1);
            if (hf == 0) {
                const float alpha = __expf(mold - mnew);
                sL[r] = sL[r] * alpha + ps;
                sM[r] = mnew;
                sA[r] = alpha;
            }
        }
        __syncthreads();

        // O = O*alpha + P @ V
        const float al0 = sA[wm0 + g];
        const float al1 = sA[wm0 + g + 8];
#pragma unroll
        for (int nf = 0; nf < 8; nf++) {
            o[nf][0] *= al0; o[nf][1] *= al0;
            o[nf][2] *= al1; o[nf][3] *= al1;
        }
#pragma unroll
        for (int ks = 0; ks < 8; ks++) {
            const int kk = ks * 8;
            uint32_t a[4];
            const float* ap = sP + (wm0 + g) * ALD + kk + t;
            a[0] = __float_as_uint(ap[0]);
            a[1] = __float_as_uint(ap[8 * ALD]);
            a[2] = __float_as_uint(ap[4]);
            a[3] = __float_as_uint(ap[8 * ALD + 4]);
#pragma unroll
            for (int nf = 0; nf < 8; nf++) {
                uint32_t bb[2];
                const float* bp = sVt + (nf * 8 + g) * ALD + kk + t;
                bb[0] = __float_as_uint(bp[0]);
                bb[1] = __float_as_uint(bp[4]);
                mma_tf32(o[nf], a, bb);
            }
        }
        __syncthreads();
    }

    // normalize + store (tf32-rounded: feeds Wp GEMM)
    const float il0 = 1.0f / sL[wm0 + g];
    const float il1 = 1.0f / sL[wm0 + g + 8];
    float* yg = y + base;
#pragma unroll
    for (int nf = 0; nf < 8; nf++) {
        const int col = nf * 8 + t * 2;
        const int r0 = q0 + wm0 + g;
        float2 o0; o0.x = tf32r(o[nf][0] * il0); o0.y = tf32r(o[nf][1] * il0);
        *(float2*)(yg + (size_t)r0 * D_MODEL + col) = o0;
        float2 o1; o1.x = tf32r(o[nf][2] * il1); o1.y = tf32r(o[nf][3] * il1);
        *(float2*)(yg + (size_t)(r0 + 8) * D_MODEL + col) = o1;
    }
}

// ===========================================================================
// launch
// ===========================================================================
extern "C" void kernel_launch(void* const* d_in, const int* in_sizes, int n_in,
                              void* d_out, int out_size) {
    const float* x   = (const float*)d_in[0];
    const float* Wk  = (const float*)d_in[1];
    const float* Wq  = (const float*)d_in[2];
    const float* Wv  = (const float*)d_in[3];
    const float* Wp  = (const float*)d_in[4];
    const float* bp  = (const float*)d_in[5];
    const float* g1  = (const float*)d_in[6];
    const float* b1  = (const float*)d_in[7];
    const float* g2  = (const float*)d_in[8];
    const float* b2  = (const float*)d_in[9];
    const float* W1  = (const float*)d_in[10];
    const float* bm1 = (const float*)d_in[11];
    const float* W2  = (const float*)d_in[12];
    const float* bm2 = (const float*)d_in[13];
    float* out = (float*)d_out;

    float* S = nullptr;
    cudaGetSymbolAddress((void**)&S, g_scratch);
    float* xn  = S + 0 * CH;
    float* xnr = S + 1 * CH;
    float* qb  = S + 2 * CH;
    float* kb  = S + 3 * CH;
    float* vb  = S + 4 * CH;
    float* yb  = S + 5 * CH;
    float* hb  = S + 6 * CH;
    float* hn  = S + 7 * CH;
    float* m1  = S + 8 * CH;   // 16M floats
    float* WqT = S + 12 * CH;
    float* WkT = S + 13 * CH;
    float* WvT = S + 14 * CH;
    float* WpT = S + 15 * CH;
    float* W1T = S + 16 * CH;  // 4M
    float* W2T = S + 20 * CH;  // 4M

    cudaFuncSetAttribute(attn_kernel, cudaFuncAttributeMaxDynamicSharedMemorySize,
                         ATT_SMEM);
    cudaFuncSetAttribute(tgemm<false>, cudaFuncAttributeMaxDynamicSharedMemorySize,
                         GEMM_SMEM);
    cudaFuncSetAttribute(tgemm<true>, cudaFuncAttributeMaxDynamicSharedMemorySize,
                         GEMM_SMEM);

    // 0) transpose weights -> [N,K], tf32-rounded
    dim3 tb(32, 8);
    transpose_kernel<<<dim3(D_MODEL/32, D_MODEL/32), tb>>>(Wq, WqT, D_MODEL, D_MODEL);
    transpose_kernel<<<dim3(D_MODEL/32, D_MODEL/32), tb>>>(Wk, WkT, D_MODEL, D_MODEL);
    transpose_kernel<<<dim3(D_MODEL/32, D_MODEL/32), tb>>>(Wv, WvT, D_MODEL, D_MODEL);
    transpose_kernel<<<dim3(D_MODEL/32, D_MODEL/32), tb>>>(Wp, WpT, D_MODEL, D_MODEL);
    transpose_kernel<<<dim3(DFF/32, D_MODEL/32),     tb>>>(W1, W1T, D_MODEL, DFF);
    transpose_kernel<<<dim3(D_MODEL/32, DFF/32),     tb>>>(W2, W2T, DFF, D_MODEL);

    // 1) xn = LN1(x): exact (residual) + rounded (GEMM A)
    ln_kernel<<<MROWS, 256>>>(x, g1, b1, xn, xnr);

    // 2) q,k,v = xnr @ W
    dim3 g1024(D_MODEL / 128, MROWS / 128);
    tgemm<false><<<g1024, 256, GEMM_SMEM>>>(xnr, WqT, qb, MROWS, D_MODEL, D_MODEL, nullptr, nullptr);
    tgemm<false><<<g1024, 256, GEMM_SMEM>>>(xnr, WkT, kb, MROWS, D_MODEL, D_MODEL, nullptr, nullptr);
    tgemm<false><<<g1024, 256, GEMM_SMEM>>>(xnr, WvT, vb, MROWS, D_MODEL, D_MODEL, nullptr, nullptr);

    // 3) flash attention (tensorized) -> yb
    dim3 ag(BATCH * NHEAD, SEQ / 64);
    attn_kernel<<<ag, 128, ATT_SMEM>>>(qb, kb, vb, yb);

    // 4) h = xn + yb @ Wp + bp
    tgemm<false><<<g1024, 256, GEMM_SMEM>>>(yb, WpT, hb, MROWS, D_MODEL, D_MODEL, bp, xn);

    // 5) hn = LN2(h), rounded only (GEMM input)
    ln_kernel<<<MROWS, 256>>>(hb, g2, b2, nullptr, hn);

    // 6) m1 = tf32(gelu(hn @ W1 + bm1))
    dim3 g4096(DFF / 128, MROWS / 128);
    tgemm<true><<<g4096, 256, GEMM_SMEM>>>(hn, W1T, m1, MROWS, DFF, D_MODEL, bm1, nullptr);

    // 7) out = hb + m1 @ W2 + bm2
    tgemm<false><<<g1024, 256, GEMM_SMEM>>>(m1, W2T, out, MROWS, D_MODEL, DFF, bm2, hb);

    (void)in_sizes; (void)n_in; (void)out_size;
}